// round 13
// baseline (speedup 1.0000x reference)
#include <cuda_runtime.h>
#include <cuda_bf16.h>

#define IMG_W 512
#define IMG_H 512
#define SUBROWS 32          // rows per warp strip
#define NTHREADS 128        // 4 warps: (colhalf = w&1, subband = w>>1)

// Zero row for out-of-image / past-strip rows: static storage -> zero
// initialized, never written; L2-resident. zbase = g_zrow+4 so
// [seg-1, seg+256] stays in-bounds for seg in {0, 256}.
__device__ __align__(16) float g_zrow[520];

// 3x3 local variance, stride 1, zero pad 1, divisor 9.
// Warp-autonomous, branch-free row loads with one-row register prefetch.
// Each lane owns TWO interleaved 4-col groups: A = seg+4*lane,
// B = seg+128+4*lane -> both LDG.128/STG.128 per row are fully coalesced
// (16B lane stride), unlike the 8-contiguous-cols layout (32B stride, 2x
// L1tex wavefronts). Vertical rolling sums per group; horizontal 3-tap via
// shuffles, A|B seam stitched with two warp broadcasts; outer boundary
// column via scalar rolling state in lanes 0/31.
__global__ __launch_bounds__(NTHREADS, 8)
void ChannelwiseVariance_85091892068508_kernel(const float* __restrict__ x,
                                               float* __restrict__ out)
{
    const int tid  = threadIdx.x;
    const int lane = tid & 31;
    const int w    = tid >> 5;
    const int colhalf = w & 1;
    const int sub     = w >> 1;
    const int seg  = colhalf * 256;                // warp's 256-col segment
    const int ca   = seg + 4 * lane;               // group A base col
    const int cb   = seg + 128 + 4 * lane;         // group B base col
    const int y0   = blockIdx.x * (2 * SUBROWS) + sub * SUBROWS;
    const int rlast = y0 + SUBROWS;                // last input row needed
    const size_t plane = (size_t)blockIdx.y * (size_t)(IMG_H * IMG_W);

    const float* const zbase = g_zrow + 4;
    const bool lane_l = (lane == 0)  && (seg != 0);          // fetch seg-1
    const bool lane_r = (lane == 31) && (seg + 256 != IMG_W); // fetch seg+256
    const float inv9 = 1.0f / 9.0f;
    const unsigned m = 0xffffffffu;

    float vpA[4], pA[4], qA[4], vpB[4], pB[4], qB[4];
    #pragma unroll
    for (int j = 0; j < 4; ++j) {
        vpA[j] = 0.f; pA[j] = 0.f; qA[j] = 0.f;
        vpB[j] = 0.f; pB[j] = 0.f; qB[j] = 0.f;
    }
    float lxp = 0.f, lp = 0.f, lq = 0.f;           // outer-left rolling state
    float rxp = 0.f, rp = 0.f, rq = 0.f;           // outer-right (lanes 0/31)

    // Prologue: prefetch row y0-1 (zero row when y0 == 0).
    const float* nrp = (y0 - 1 >= 0) ? (x + plane + (size_t)(y0 - 1) * IMG_W)
                                     : zbase;
    float4 naA = *reinterpret_cast<const float4*>(nrp + ca);
    float4 naB = *reinterpret_cast<const float4*>(nrp + cb);
    float nl = lane_l ? nrp[seg - 1]   : 0.0f;
    float nr = lane_r ? nrp[seg + 256] : 0.0f;

    #pragma unroll 2
    for (int it = 0; it < SUBROWS + 2; ++it) {
        const int r = y0 - 1 + it;

        // Consume prefetched row r.
        const float4 vA = naA, vB = naB;
        const float lxn = nl, rxn = nr;

        // Prefetch row r+1 (branch-free; zero row past image or strip end).
        const int rn = r + 1;
        const bool fetch = (rn < IMG_H) && (rn <= rlast);
        const float* prp = fetch ? (x + plane + (size_t)rn * IMG_W) : zbase;
        naA = *reinterpret_cast<const float4*>(prp + ca);
        naB = *reinterpret_cast<const float4*>(prp + cb);
        nl = lane_l ? prp[seg - 1]   : 0.0f;
        nr = lane_r ? prp[seg + 256] : 0.0f;

        float vcA[4] = {vA.x, vA.y, vA.z, vA.w};
        float vcB[4] = {vB.x, vB.y, vB.z, vB.w};

        // Vertical 3-sums for output row r-1, roll state forward.
        float S1A[4], S2A[4], S1B[4], S2B[4];
        #pragma unroll
        for (int j = 0; j < 4; ++j) {
            const float sqa = vcA[j] * vcA[j];
            S1A[j] = pA[j] + vcA[j];
            S2A[j] = qA[j] + sqa;
            pA[j]  = vpA[j] + vcA[j];
            qA[j]  = fmaf(vpA[j], vpA[j], sqa);
            vpA[j] = vcA[j];

            const float sqb = vcB[j] * vcB[j];
            S1B[j] = pB[j] + vcB[j];
            S2B[j] = qB[j] + sqb;
            pB[j]  = vpB[j] + vcB[j];
            qB[j]  = fmaf(vpB[j], vpB[j], sqb);
            vpB[j] = vcB[j];
        }
        // Outer boundary scalars (live in lanes 0 / 31).
        const float lsq = lxn * lxn, rsq = rxn * rxn;
        const float lS1 = lp + lxn, lS2 = lq + lsq;
        const float rS1 = rp + rxn, rS2 = rq + rsq;
        lp = lxp + lxn; lq = fmaf(lxp, lxp, lsq); lxp = lxn;
        rp = rxp + rxn; rq = fmaf(rxp, rxp, rsq); rxp = rxn;

        if (it >= 2) {
            // Cross-group seam broadcasts (warp-uniform).
            const float bS1B0 = __shfl_sync(m, S1B[0], 0);
            const float bS2B0 = __shfl_sync(m, S2B[0], 0);
            const float bS1A3 = __shfl_sync(m, S1A[3], 31);
            const float bS2A3 = __shfl_sync(m, S2A[3], 31);

            float lA1 = __shfl_up_sync(m, S1A[3], 1);
            float lA2 = __shfl_up_sync(m, S2A[3], 1);
            float rA1 = __shfl_down_sync(m, S1A[0], 1);
            float rA2 = __shfl_down_sync(m, S2A[0], 1);
            float lB1 = __shfl_up_sync(m, S1B[3], 1);
            float lB2 = __shfl_up_sync(m, S2B[3], 1);
            float rB1 = __shfl_down_sync(m, S1B[0], 1);
            float rB2 = __shfl_down_sync(m, S2B[0], 1);
            if (lane == 0)  { lA1 = lS1;   lA2 = lS2;   lB1 = bS1A3; lB2 = bS2A3; }
            if (lane == 31) { rA1 = bS1B0; rA2 = bS2B0; rB1 = rS1;   rB2 = rS2;   }

            float oA[4], oB[4];
            {   // group A: neighbors [lA, S1A[0..3], rA]
                float t1 = lA1 + S1A[0] + S1A[1];
                float t2 = lA2 + S2A[0] + S2A[1];
                float mm = t1 * inv9; oA[0] = fmaf(-mm, mm, t2 * inv9);
                t1 = S1A[0] + S1A[1] + S1A[2];
                t2 = S2A[0] + S2A[1] + S2A[2];
                mm = t1 * inv9; oA[1] = fmaf(-mm, mm, t2 * inv9);
                t1 = S1A[1] + S1A[2] + S1A[3];
                t2 = S2A[1] + S2A[2] + S2A[3];
                mm = t1 * inv9; oA[2] = fmaf(-mm, mm, t2 * inv9);
                t1 = S1A[2] + S1A[3] + rA1;
                t2 = S2A[2] + S2A[3] + rA2;
                mm = t1 * inv9; oA[3] = fmaf(-mm, mm, t2 * inv9);
            }
            {   // group B: neighbors [lB, S1B[0..3], rB]
                float t1 = lB1 + S1B[0] + S1B[1];
                float t2 = lB2 + S2B[0] + S2B[1];
                float mm = t1 * inv9; oB[0] = fmaf(-mm, mm, t2 * inv9);
                t1 = S1B[0] + S1B[1] + S1B[2];
                t2 = S2B[0] + S2B[1] + S2B[2];
                mm = t1 * inv9; oB[1] = fmaf(-mm, mm, t2 * inv9);
                t1 = S1B[1] + S1B[2] + S1B[3];
                t2 = S2B[1] + S2B[2] + S2B[3];
                mm = t1 * inv9; oB[2] = fmaf(-mm, mm, t2 * inv9);
                t1 = S1B[2] + S1B[3] + rB1;
                t2 = S2B[2] + S2B[3] + rB2;
                mm = t1 * inv9; oB[3] = fmaf(-mm, mm, t2 * inv9);
            }

            const int y = r - 1;
            float* obase = out + plane + (size_t)y * IMG_W;
            __stcs(reinterpret_cast<float4*>(obase + ca),
                   make_float4(oA[0], oA[1], oA[2], oA[3]));
            __stcs(reinterpret_cast<float4*>(obase + cb),
                   make_float4(oB[0], oB[1], oB[2], oB[3]));
        }
    }
}

extern "C" void kernel_launch(void* const* d_in, const int* in_sizes, int n_in,
                              void* d_out, int out_size)
{
    const float* x = (const float*)d_in[0];
    float* out = (float*)d_out;

    const int planes = in_sizes[0] / (IMG_H * IMG_W);   // 8*32 = 256
    dim3 grid(IMG_H / (2 * SUBROWS), planes);           // (8, 256) = 2048 blocks
    dim3 block(NTHREADS);
    ChannelwiseVariance_85091892068508_kernel<<<grid, block>>>(x, out);
}

// round 14
// speedup vs baseline: 1.0043x; 1.0043x over previous
#include <cuda_runtime.h>
#include <cuda_bf16.h>

#define IMG_W 512
#define IMG_H 512
#define SUBROWS 32          // rows per block strip
#define NTHREADS 128        // 4 warps; warp w owns cols [w*128, w*128+128)

// Zero row for out-of-image / past-strip rows: static storage -> zero
// initialized, never written; L2-resident. zbase = g_zrow+4 so
// [col-1, col+4] stays in-bounds for col in [0,508].
__device__ __align__(16) float g_zrow[520];

// 3x3 local variance, stride 1, zero pad 1, divisor 9.
// Warp-autonomous, 4 cols/lane (fully coalesced LDG.128), branch-free row
// loads with a TWO-row register prefetch pipeline. Low register footprint ->
// 9 CTAs/SM -> more warps -> more loads in flight (bandwidth = concurrency).
// Rolling state: vp (prev row), p (2-row sum), q (2-row sq-sum). Vertical
// 3-sum then horizontal 3-tap via shuffles; warp-boundary column via scalar
// rolling state in lanes 0/31.
__global__ __launch_bounds__(NTHREADS, 9)
void ChannelwiseVariance_85091892068508_kernel(const float* __restrict__ x,
                                               float* __restrict__ out)
{
    const int tid  = threadIdx.x;
    const int lane = tid & 31;
    const int w    = tid >> 5;
    const int col  = w * 128 + lane * 4;           // first of 4 owned columns
    const int y0   = blockIdx.x * SUBROWS;         // strip's first output row
    const int rlast = y0 + SUBROWS;                // last input row needed
    const size_t plane = (size_t)blockIdx.y * (size_t)(IMG_H * IMG_W);

    const float* const zbase = g_zrow + 4;
    const bool lane_l = (lane == 0)  && (col != 0);
    const bool lane_r = (lane == 31) && (col + 4 != IMG_W);
    const float inv9 = 1.0f / 9.0f;
    const unsigned fm = 0xffffffffu;

    float vp[4], p[4], q[4];
    #pragma unroll
    for (int j = 0; j < 4; ++j) { vp[j] = 0.f; p[j] = 0.f; q[j] = 0.f; }
    float lxp = 0.f, lp = 0.f, lq = 0.f;           // boundary rolling state
    float rxp = 0.f, rp = 0.f, rq = 0.f;           // (lanes 0 / 31)

    // Branch-free row-pointer select.
    auto rowptr = [&](int rn) -> const float* {
        const bool fetch = (rn >= 0) && (rn < IMG_H) && (rn <= rlast);
        return fetch ? (x + plane + (size_t)rn * IMG_W) : zbase;
    };

    // Prologue: two prefetch stages (rows y0-1 and y0).
    const float* rp0 = rowptr(y0 - 1);
    float4 n1 = *reinterpret_cast<const float4*>(rp0 + col);
    float  nl1 = lane_l ? rp0[col - 1] : 0.0f;
    float  nr1 = lane_r ? rp0[col + 4] : 0.0f;

    const float* rp1 = rowptr(y0);
    float4 n2 = *reinterpret_cast<const float4*>(rp1 + col);
    float  nl2 = lane_l ? rp1[col - 1] : 0.0f;
    float  nr2 = lane_r ? rp1[col + 4] : 0.0f;

    #pragma unroll 2
    for (int it = 0; it < SUBROWS + 2; ++it) {
        const int r = y0 - 1 + it;

        // Consume stage-1 (row r); shift stage-2 -> stage-1.
        const float4 v = n1;
        const float lxn = nl1, rxn = nr1;
        n1 = n2; nl1 = nl2; nr1 = nr2;

        // Issue stage-2 prefetch for row r+2.
        const float* prp = rowptr(r + 2);
        n2  = *reinterpret_cast<const float4*>(prp + col);
        nl2 = lane_l ? prp[col - 1] : 0.0f;
        nr2 = lane_r ? prp[col + 4] : 0.0f;

        float vc[4] = {v.x, v.y, v.z, v.w};

        // Vertical 3-sums for output row r-1, roll state forward.
        float S1[4], S2[4];
        #pragma unroll
        for (int j = 0; j < 4; ++j) {
            const float sq = vc[j] * vc[j];
            S1[j] = p[j] + vc[j];
            S2[j] = q[j] + sq;
            p[j]  = vp[j] + vc[j];
            q[j]  = fmaf(vp[j], vp[j], sq);
            vp[j] = vc[j];
        }
        // Boundary scalars (live in lanes 0 / 31).
        const float lsq = lxn * lxn, rsq = rxn * rxn;
        const float lS1 = lp + lxn, lS2 = lq + lsq;
        const float rS1 = rp + rxn, rS2 = rq + rsq;
        lp = lxp + lxn; lq = fmaf(lxp, lxp, lsq); lxp = lxn;
        rp = rxp + rxn; rq = fmaf(rxp, rxp, rsq); rxp = rxn;

        if (it >= 2) {
            // Horizontal halo of vertical sums via shuffles.
            float sv_l = __shfl_up_sync(fm, S1[3], 1);
            float sq_l = __shfl_up_sync(fm, S2[3], 1);
            float sv_r = __shfl_down_sync(fm, S1[0], 1);
            float sq_r = __shfl_down_sync(fm, S2[0], 1);
            if (lane == 0)  { sv_l = lS1; sq_l = lS2; }
            if (lane == 31) { sv_r = rS1; sq_r = rS2; }

            float o[4];
            {
                const float t1 = sv_l + S1[0] + S1[1];
                const float t2 = sq_l + S2[0] + S2[1];
                const float m = t1 * inv9; o[0] = fmaf(-m, m, t2 * inv9);
            }
            {
                const float t1 = S1[0] + S1[1] + S1[2];
                const float t2 = S2[0] + S2[1] + S2[2];
                const float m = t1 * inv9; o[1] = fmaf(-m, m, t2 * inv9);
            }
            {
                const float t1 = S1[1] + S1[2] + S1[3];
                const float t2 = S2[1] + S2[2] + S2[3];
                const float m = t1 * inv9; o[2] = fmaf(-m, m, t2 * inv9);
            }
            {
                const float t1 = S1[2] + S1[3] + sv_r;
                const float t2 = S2[2] + S2[3] + sq_r;
                const float m = t1 * inv9; o[3] = fmaf(-m, m, t2 * inv9);
            }

            const int y = r - 1;
            __stcs(reinterpret_cast<float4*>(out + plane + (size_t)y * IMG_W + col),
                   make_float4(o[0], o[1], o[2], o[3]));
        }
    }
}

extern "C" void kernel_launch(void* const* d_in, const int* in_sizes, int n_in,
                              void* d_out, int out_size)
{
    const float* x = (const float*)d_in[0];
    float* out = (float*)d_out;

    const int planes = in_sizes[0] / (IMG_H * IMG_W);   // 8*32 = 256
    dim3 grid(IMG_H / SUBROWS, planes);                 // (16, 256) = 4096 blocks
    dim3 block(NTHREADS);
    ChannelwiseVariance_85091892068508_kernel<<<grid, block>>>(x, out);
}